// round 2
// baseline (speedup 1.0000x reference)
#include <cuda_runtime.h>
#include <math.h>

#define B_   256
#define T_   512
#define D_   256
#define K_   256

// Scratch for the precomputed input projection xU [B, T, K] (134 MB, static device mem).
__device__ float g_xu[(size_t)B_ * T_ * K_];

// =====================================================================
// Kernel 1: xU = X @ U + b    (M = B*T = 131072, Kdim = 256, N = 256)
// Classic tiled SGEMM: 128x128 block tile, 8x8 per-thread tile, BK=8.
// =====================================================================
#define BM 128
#define BN 128
#define BK 8
#define TM 8
#define TN 8

__global__ __launch_bounds__(256) void xu_gemm_kernel(
    const float* __restrict__ X,     // [B*T, D]
    const float* __restrict__ U,     // [D, K]
    const float* __restrict__ bias)  // [K]
{
    __shared__ float As[BK][BM + 4];   // transposed A tile, padded vs bank conflicts
    __shared__ float Bs[BK][BN];

    const int m0 = blockIdx.x * BM;
    const int n0 = blockIdx.y * BN;
    const int tid = (int)threadIdx.x;
    const int tx = tid & 15;          // 0..15  (N direction)
    const int ty = tid >> 4;          // 0..15  (M direction)

    float acc[TM][TN];
#pragma unroll
    for (int i = 0; i < TM; i++)
#pragma unroll
        for (int j = 0; j < TN; j++) acc[i][j] = 0.0f;

    // A-load mapping: one float4 per thread (128 rows x 8 cols = 256 float4)
    const int a_row = tid >> 1;           // 0..127
    const int a_col = (tid & 1) * 4;      // 0 or 4
    // B-load mapping: one float4 per thread (8 rows x 128 cols = 256 float4)
    const int b_row = tid >> 5;           // 0..7
    const int b_col = (tid & 31) * 4;     // 0..124

    for (int k0 = 0; k0 < D_; k0 += BK) {
        float4 av = *(const float4*)&X[(size_t)(m0 + a_row) * D_ + (k0 + a_col)];
        float4 bv = *(const float4*)&U[(size_t)(k0 + b_row) * K_ + (n0 + b_col)];

        As[a_col + 0][a_row] = av.x;
        As[a_col + 1][a_row] = av.y;
        As[a_col + 2][a_row] = av.z;
        As[a_col + 3][a_row] = av.w;
        *(float4*)&Bs[b_row][b_col] = bv;
        __syncthreads();

#pragma unroll
        for (int kk = 0; kk < BK; kk++) {
            float a[TM], b[TN];
            float4 a0 = *(const float4*)&As[kk][ty * TM + 0];
            float4 a1 = *(const float4*)&As[kk][ty * TM + 4];
            a[0] = a0.x; a[1] = a0.y; a[2] = a0.z; a[3] = a0.w;
            a[4] = a1.x; a[5] = a1.y; a[6] = a1.z; a[7] = a1.w;
            float4 b0 = *(const float4*)&Bs[kk][tx * TN + 0];
            float4 b1 = *(const float4*)&Bs[kk][tx * TN + 4];
            b[0] = b0.x; b[1] = b0.y; b[2] = b0.z; b[3] = b0.w;
            b[4] = b1.x; b[5] = b1.y; b[6] = b1.z; b[7] = b1.w;
#pragma unroll
            for (int i = 0; i < TM; i++)
#pragma unroll
                for (int j = 0; j < TN; j++)
                    acc[i][j] = fmaf(a[i], b[j], acc[i][j]);
        }
        __syncthreads();
    }

    // Epilogue: add bias, store to g_xu
    float breg[TN];
#pragma unroll
    for (int j = 0; j < TN; j++) breg[j] = bias[n0 + tx * TN + j];

#pragma unroll
    for (int i = 0; i < TM; i++) {
        const size_t m = (size_t)(m0 + ty * TM + i);
        float4 v0, v1;
        v0.x = acc[i][0] + breg[0];
        v0.y = acc[i][1] + breg[1];
        v0.z = acc[i][2] + breg[2];
        v0.w = acc[i][3] + breg[3];
        v1.x = acc[i][4] + breg[4];
        v1.y = acc[i][5] + breg[5];
        v1.z = acc[i][6] + breg[6];
        v1.w = acc[i][7] + breg[7];
        *(float4*)&g_xu[m * K_ + (n0 + tx * TN + 0)] = v0;
        *(float4*)&g_xu[m * K_ + (n0 + tx * TN + 4)] = v1;
    }
}

// =====================================================================
// Kernel 2: persistent per-batch recurrence.
//   h_t[b,:] = tanh(xu[b,t,:] + h_{t-1}[b,:] @ W)
// 128 blocks x 256 threads; block owns 2 batches for all 512 steps.
// W rows 0..127 live in smem (128 KB); rows 128..255 live in registers
// (128 floats/thread). Reduction over j split across 4 warp-groups.
// Thread (g, c): g = tid>>6 (j-group), c = tid&63 (columns 4c..4c+3).
//   group g covers j in [32g, 32g+32) from smem and [128+32g, 128+32g+32)
//   from registers; partials summed through smem.
// =====================================================================
#define RNN_SMEM_FLOATS (128 * 256 + 512 + 4 * 2 * 256)
#define RNN_SMEM_BYTES  (RNN_SMEM_FLOATS * 4)

__global__ __launch_bounds__(256, 1) void rnn_recurrence_kernel(
    const float* __restrict__ W,    // [K, K] row-major: W[j*K + k]
    float* __restrict__ out)        // [B, K]
{
    extern __shared__ float sm[];
    float* Wsm  = sm;                         // 128*256 floats
    float* hs   = sm + 128 * 256;             // 512 floats: hs[2*j + b]
    float* part = hs + 512;                   // 4*2*256 floats: part[(g*2+b)*256 + k]

    const int tid = (int)threadIdx.x;
    const int g   = tid >> 6;        // 0..3
    const int c   = tid & 63;        // 0..63
    const int col = c * 4;           // base column (k)

    const int b0 = blockIdx.x * 2;
    const int b1 = b0 + 1;

    // --- Load W rows 0..127 into smem (each thread: 32 float4) ---
    for (int i = tid; i < 128 * 64; i += 256) {
        const int row = i >> 6;
        const int c4  = (i & 63) * 4;
        *(float4*)&Wsm[row * 256 + c4] = *(const float4*)&W[row * 256 + c4];
    }
    // --- Load W rows 128..255 into registers: this thread's group+columns ---
    float4 wreg[32];
#pragma unroll
    for (int jj = 0; jj < 32; jj++) {
        const int j = 128 + g * 32 + jj;
        wreg[jj] = *(const float4*)&W[j * 256 + col];
    }
    // --- h0 = 0 ---
    hs[2 * tid]     = 0.0f;
    hs[2 * tid + 1] = 0.0f;
    __syncthreads();

    const float* xu0p = g_xu + ((size_t)b0 * T_) * K_ + tid;
    const float* xu1p = g_xu + ((size_t)b1 * T_) * K_ + tid;

    float h0n = 0.0f, h1n = 0.0f;

    for (int ts = 0; ts < T_; ts++) {
        // Prefetch this step's xu values (latency hidden behind the FMA loops)
        const float xv0 = xu0p[(size_t)ts * K_];
        const float xv1 = xu1p[(size_t)ts * K_];

        float4 acc0 = make_float4(0.f, 0.f, 0.f, 0.f);
        float4 acc1 = make_float4(0.f, 0.f, 0.f, 0.f);
        const int js = g * 32;

        // smem W rows [32g, 32g+32)
#pragma unroll
        for (int jj = 0; jj < 32; jj++) {
            const int j = js + jj;
            const float4 w  = *(const float4*)&Wsm[j * 256 + col];
            const float2 h2 = *(const float2*)&hs[2 * j];
            acc0.x = fmaf(w.x, h2.x, acc0.x);
            acc0.y = fmaf(w.y, h2.x, acc0.y);
            acc0.z = fmaf(w.z, h2.x, acc0.z);
            acc0.w = fmaf(w.w, h2.x, acc0.w);
            acc1.x = fmaf(w.x, h2.y, acc1.x);
            acc1.y = fmaf(w.y, h2.y, acc1.y);
            acc1.z = fmaf(w.z, h2.y, acc1.z);
            acc1.w = fmaf(w.w, h2.y, acc1.w);
        }
        // register W rows [128+32g, 128+32g+32)
#pragma unroll
        for (int jj = 0; jj < 32; jj++) {
            const int j = 128 + js + jj;
            const float4 w  = wreg[jj];
            const float2 h2 = *(const float2*)&hs[2 * j];
            acc0.x = fmaf(w.x, h2.x, acc0.x);
            acc0.y = fmaf(w.y, h2.x, acc0.y);
            acc0.z = fmaf(w.z, h2.x, acc0.z);
            acc0.w = fmaf(w.w, h2.x, acc0.w);
            acc1.x = fmaf(w.x, h2.y, acc1.x);
            acc1.y = fmaf(w.y, h2.y, acc1.y);
            acc1.z = fmaf(w.z, h2.y, acc1.z);
            acc1.w = fmaf(w.w, h2.y, acc1.w);
        }

        // write partials: part[(g*2 + b)*256 + col]
        *(float4*)&part[(g * 2 + 0) * 256 + col] = acc0;
        *(float4*)&part[(g * 2 + 1) * 256 + col] = acc1;
        __syncthreads();

        // reduce the 4 group-partials; thread tid owns column k = tid for both batches
        const float s0 = part[0 * 512 + tid] + part[1 * 512 + tid] +
                         part[2 * 512 + tid] + part[3 * 512 + tid];
        const float s1 = part[0 * 512 + 256 + tid] + part[1 * 512 + 256 + tid] +
                         part[2 * 512 + 256 + tid] + part[3 * 512 + 256 + tid];

        h0n = tanhf(xv0 + s0);
        h1n = tanhf(xv1 + s1);

        // store new h (old h reads all completed before the barrier above)
        *(float2*)&hs[2 * tid] = make_float2(h0n, h1n);
        __syncthreads();
    }

    // final hidden state -> out [B, K] (thread tid owns column tid)
    out[(size_t)b0 * K_ + tid] = h0n;
    out[(size_t)b1 * K_ + tid] = h1n;
}

// =====================================================================
// Harness entry
// metadata order: inputs [B,T,D] f32, U [D,K] f32, W [K,K] f32, b [K] f32
// output: [B,1,K] f32
// =====================================================================
extern "C" void kernel_launch(void* const* d_in, const int* in_sizes, int n_in,
                              void* d_out, int out_size) {
    const float* X    = (const float*)d_in[0];
    const float* U    = (const float*)d_in[1];
    const float* W    = (const float*)d_in[2];
    const float* bias = (const float*)d_in[3];
    float* out = (float*)d_out;

    // Opt in to 138 KB dynamic smem for the recurrence kernel. Not a stream
    // operation -> legal under graph capture; called every launch (idempotent,
    // keeps kernel_launch deterministic and stateless).
    cudaError_t attr_rc = cudaFuncSetAttribute(
        rnn_recurrence_kernel,
        cudaFuncAttributeMaxDynamicSharedMemorySize,
        RNN_SMEM_BYTES);
    (void)attr_rc;

    dim3 gemm_grid(B_ * T_ / BM, K_ / BN);   // (1024, 2)
    xu_gemm_kernel<<<gemm_grid, 256>>>(X, U, bias);

    rnn_recurrence_kernel<<<128, 256, RNN_SMEM_BYTES>>>(W, out);
}

// round 4
// speedup vs baseline: 1.0836x; 1.0836x over previous
#include <cuda_runtime.h>
#include <math.h>

#define B_   256
#define T_   512
#define D_   256
#define K_   256

// Scratch for the precomputed input projection xU [B, T, K] (134 MB, static device mem).
__device__ float g_xu[(size_t)B_ * T_ * K_];

// =====================================================================
// Kernel 1: xU = X @ U + b    (M = B*T = 131072, Kdim = 256, N = 256)
// Tiled SGEMM: 128x128 block tile, 8x8 per-thread tile, BK=8,
// register-prefetch double buffering of the global loads.
// =====================================================================
#define BM 128
#define BN 128
#define BK 8
#define TM 8
#define TN 8

__global__ __launch_bounds__(256) void xu_gemm_kernel(
    const float* __restrict__ X,     // [B*T, D]
    const float* __restrict__ U,     // [D, K]
    const float* __restrict__ bias)  // [K]
{
    __shared__ float As[BK][BM + 4];   // transposed A tile, padded vs bank conflicts
    __shared__ float Bs[BK][BN];

    const int m0 = blockIdx.x * BM;
    const int n0 = blockIdx.y * BN;
    const int tid = (int)threadIdx.x;
    const int tx = tid & 15;          // 0..15  (N direction)
    const int ty = tid >> 4;          // 0..15  (M direction)

    float acc[TM][TN];
#pragma unroll
    for (int i = 0; i < TM; i++)
#pragma unroll
        for (int j = 0; j < TN; j++) acc[i][j] = 0.0f;

    // A-load mapping: one float4 per thread (128 rows x 8 cols = 256 float4)
    const int a_row = tid >> 1;           // 0..127
    const int a_col = (tid & 1) * 4;      // 0 or 4
    // B-load mapping: one float4 per thread (8 rows x 128 cols = 256 float4)
    const int b_row = tid >> 5;           // 0..7
    const int b_col = (tid & 31) * 4;     // 0..124

    // Prefetch first tile into registers
    float4 av = *(const float4*)&X[(size_t)(m0 + a_row) * D_ + a_col];
    float4 bv = *(const float4*)&U[(size_t)b_row * K_ + (n0 + b_col)];

    for (int k0 = 0; k0 < D_; k0 += BK) {
        // Commit the prefetched tile to smem
        As[a_col + 0][a_row] = av.x;
        As[a_col + 1][a_row] = av.y;
        As[a_col + 2][a_row] = av.z;
        As[a_col + 3][a_row] = av.w;
        *(float4*)&Bs[b_row][b_col] = bv;
        __syncthreads();

        // Prefetch next tile while computing this one
        if (k0 + BK < D_) {
            av = *(const float4*)&X[(size_t)(m0 + a_row) * D_ + (k0 + BK + a_col)];
            bv = *(const float4*)&U[(size_t)(k0 + BK + b_row) * K_ + (n0 + b_col)];
        }

#pragma unroll
        for (int kk = 0; kk < BK; kk++) {
            float a[TM], b[TN];
            float4 a0 = *(const float4*)&As[kk][ty * TM + 0];
            float4 a1 = *(const float4*)&As[kk][ty * TM + 4];
            a[0] = a0.x; a[1] = a0.y; a[2] = a0.z; a[3] = a0.w;
            a[4] = a1.x; a[5] = a1.y; a[6] = a1.z; a[7] = a1.w;
            float4 b0 = *(const float4*)&Bs[kk][tx * TN + 0];
            float4 b1 = *(const float4*)&Bs[kk][tx * TN + 4];
            b[0] = b0.x; b[1] = b0.y; b[2] = b0.z; b[3] = b0.w;
            b[4] = b1.x; b[5] = b1.y; b[6] = b1.z; b[7] = b1.w;
#pragma unroll
            for (int i = 0; i < TM; i++)
#pragma unroll
                for (int j = 0; j < TN; j++)
                    acc[i][j] = fmaf(a[i], b[j], acc[i][j]);
        }
        __syncthreads();
    }

    // Epilogue: add bias, store to g_xu
    float breg[TN];
#pragma unroll
    for (int j = 0; j < TN; j++) breg[j] = bias[n0 + tx * TN + j];

#pragma unroll
    for (int i = 0; i < TM; i++) {
        const size_t m = (size_t)(m0 + ty * TM + i);
        float4 v0, v1;
        v0.x = acc[i][0] + breg[0];
        v0.y = acc[i][1] + breg[1];
        v0.z = acc[i][2] + breg[2];
        v0.w = acc[i][3] + breg[3];
        v1.x = acc[i][4] + breg[4];
        v1.y = acc[i][5] + breg[5];
        v1.z = acc[i][6] + breg[6];
        v1.w = acc[i][7] + breg[7];
        *(float4*)&g_xu[m * K_ + (n0 + tx * TN + 0)] = v0;
        *(float4*)&g_xu[m * K_ + (n0 + tx * TN + 4)] = v1;
    }
}

// =====================================================================
// Kernel 2: persistent per-batch recurrence, 512 threads/block.
//   h_t[b,:] = tanh(xu[b,t,:] + h_{t-1}[b,:] @ W)
// 128 blocks; block owns batches {2bx, 2bx+1} for all 512 steps.
// W rows 0..127 in smem (128 KB); rows 128..255 in registers
// (64 floats/thread). Thread (g, c): g = tid>>6 in 0..7 (j-group),
// c = tid&63 (columns 4c..4c+3). Group g covers j in [16g,16g+16)
// from smem and [128+16g, 128+16g+16) from registers.
// h stored as two per-batch arrays -> float4 h loads (4 j's per LDS).
// Partials (8 groups x 2 batches x 256 cols) reduced through smem.
// =====================================================================
#define RNN_SMEM_FLOATS (128 * 256 + 2 * 256 + 16 * 256)
#define RNN_SMEM_BYTES  (RNN_SMEM_FLOATS * 4)

__global__ __launch_bounds__(512, 1) void rnn_recurrence_kernel(
    const float* __restrict__ W,    // [K, K] row-major: W[j*K + k]
    float* __restrict__ out)        // [B, K]
{
    extern __shared__ float sm[];
    float* Wsm  = sm;                  // 128*256 floats
    float* hs0  = sm + 128 * 256;      // 256 floats: h for batch b0
    float* hs1  = hs0 + 256;           // 256 floats: h for batch b1
    float* part = hs1 + 256;           // 16*256 floats: part[(g*2+b)*256 + k]

    const int tid = (int)threadIdx.x;
    const int g   = tid >> 6;        // 0..7
    const int c   = tid & 63;        // 0..63
    const int col = c * 4;           // base column (k)
    const int b0  = blockIdx.x * 2;

    // --- Load W rows 0..127 into smem (512 threads x 16 float4) ---
    for (int i = tid; i < 128 * 64; i += 512) {
        const int row = i >> 6;
        const int c4  = (i & 63) * 4;
        *(float4*)&Wsm[row * 256 + c4] = *(const float4*)&W[row * 256 + c4];
    }
    // --- W rows [128+16g, 128+16g+16) into registers for this thread's cols ---
    float4 wreg[16];
#pragma unroll
    for (int jj = 0; jj < 16; jj++) {
        wreg[jj] = *(const float4*)&W[(128 + g * 16 + jj) * 256 + col];
    }
    // --- h0 = 0 ---
    if (tid < 256) { hs0[tid] = 0.0f; hs1[tid] = 0.0f; }
    __syncthreads();

    // Reduce-phase ownership: thread -> (batch rb, column rk)
    const int rb = tid >> 8;         // 0 or 1
    const int rk = tid & 255;        // 0..255
    const float* xup = g_xu + ((size_t)(b0 + rb) * T_) * K_ + rk;

    const int js = g * 16;
    float hn = 0.0f;

    for (int ts = 0; ts < T_; ts++) {
        // Issue this step's xu load early; consumed only after barrier 1.
        const float xv = xup[(size_t)ts * K_];

        float4 acc0 = make_float4(0.f, 0.f, 0.f, 0.f);
        float4 acc1 = make_float4(0.f, 0.f, 0.f, 0.f);

        // smem W rows [16g, 16g+16), h loaded as float4 (4 j's per load)
#pragma unroll
        for (int jj = 0; jj < 16; jj += 4) {
            const float4 h0 = *(const float4*)&hs0[js + jj];
            const float4 h1 = *(const float4*)&hs1[js + jj];
            {
                const float4 w = *(const float4*)&Wsm[(js + jj + 0) * 256 + col];
                acc0.x = fmaf(w.x, h0.x, acc0.x); acc0.y = fmaf(w.y, h0.x, acc0.y);
                acc0.z = fmaf(w.z, h0.x, acc0.z); acc0.w = fmaf(w.w, h0.x, acc0.w);
                acc1.x = fmaf(w.x, h1.x, acc1.x); acc1.y = fmaf(w.y, h1.x, acc1.y);
                acc1.z = fmaf(w.z, h1.x, acc1.z); acc1.w = fmaf(w.w, h1.x, acc1.w);
            }
            {
                const float4 w = *(const float4*)&Wsm[(js + jj + 1) * 256 + col];
                acc0.x = fmaf(w.x, h0.y, acc0.x); acc0.y = fmaf(w.y, h0.y, acc0.y);
                acc0.z = fmaf(w.z, h0.y, acc0.z); acc0.w = fmaf(w.w, h0.y, acc0.w);
                acc1.x = fmaf(w.x, h1.y, acc1.x); acc1.y = fmaf(w.y, h1.y, acc1.y);
                acc1.z = fmaf(w.z, h1.y, acc1.z); acc1.w = fmaf(w.w, h1.y, acc1.w);
            }
            {
                const float4 w = *(const float4*)&Wsm[(js + jj + 2) * 256 + col];
                acc0.x = fmaf(w.x, h0.z, acc0.x); acc0.y = fmaf(w.y, h0.z, acc0.y);
                acc0.z = fmaf(w.z, h0.z, acc0.z); acc0.w = fmaf(w.w, h0.z, acc0.w);
                acc1.x = fmaf(w.x, h1.z, acc1.x); acc1.y = fmaf(w.y, h1.z, acc1.y);
                acc1.z = fmaf(w.z, h1.z, acc1.z); acc1.w = fmaf(w.w, h1.z, acc1.w);
            }
            {
                const float4 w = *(const float4*)&Wsm[(js + jj + 3) * 256 + col];
                acc0.x = fmaf(w.x, h0.w, acc0.x); acc0.y = fmaf(w.y, h0.w, acc0.y);
                acc0.z = fmaf(w.z, h0.w, acc0.z); acc0.w = fmaf(w.w, h0.w, acc0.w);
                acc1.x = fmaf(w.x, h1.w, acc1.x); acc1.y = fmaf(w.y, h1.w, acc1.y);
                acc1.z = fmaf(w.z, h1.w, acc1.z); acc1.w = fmaf(w.w, h1.w, acc1.w);
            }
        }
        // register W rows [128+16g, 128+16g+16)
#pragma unroll
        for (int jj = 0; jj < 16; jj += 4) {
            const float4 h0 = *(const float4*)&hs0[128 + js + jj];
            const float4 h1 = *(const float4*)&hs1[128 + js + jj];
            {
                const float4 w = wreg[jj + 0];
                acc0.x = fmaf(w.x, h0.x, acc0.x); acc0.y = fmaf(w.y, h0.x, acc0.y);
                acc0.z = fmaf(w.z, h0.x, acc0.z); acc0.w = fmaf(w.w, h0.x, acc0.w);
                acc1.x = fmaf(w.x, h1.x, acc1.x); acc1.y = fmaf(w.y, h1.x, acc1.y);
                acc1.z = fmaf(w.z, h1.x, acc1.z); acc1.w = fmaf(w.w, h1.x, acc1.w);
            }
            {
                const float4 w = wreg[jj + 1];
                acc0.x = fmaf(w.x, h0.y, acc0.x); acc0.y = fmaf(w.y, h0.y, acc0.y);
                acc0.z = fmaf(w.z, h0.y, acc0.z); acc0.w = fmaf(w.w, h0.y, acc0.w);
                acc1.x = fmaf(w.x, h1.y, acc1.x); acc1.y = fmaf(w.y, h1.y, acc1.y);
                acc1.z = fmaf(w.z, h1.y, acc1.z); acc1.w = fmaf(w.w, h1.y, acc1.w);
            }
            {
                const float4 w = wreg[jj + 2];
                acc0.x = fmaf(w.x, h0.z, acc0.x); acc0.y = fmaf(w.y, h0.z, acc0.y);
                acc0.z = fmaf(w.z, h0.z, acc0.z); acc0.w = fmaf(w.w, h0.z, acc0.w);
                acc1.x = fmaf(w.x, h1.z, acc1.x); acc1.y = fmaf(w.y, h1.z, acc1.y);
                acc1.z = fmaf(w.z, h1.z, acc1.z); acc1.w = fmaf(w.w, h1.z, acc1.w);
            }
            {
                const float4 w = wreg[jj + 3];
                acc0.x = fmaf(w.x, h0.w, acc0.x); acc0.y = fmaf(w.y, h0.w, acc0.y);
                acc0.z = fmaf(w.z, h0.w, acc0.z); acc0.w = fmaf(w.w, h0.w, acc0.w);
                acc1.x = fmaf(w.x, h1.w, acc1.x); acc1.y = fmaf(w.y, h1.w, acc1.y);
                acc1.z = fmaf(w.z, h1.w, acc1.z); acc1.w = fmaf(w.w, h1.w, acc1.w);
            }
        }

        // write partials: part[(g*2 + b)*256 + col]
        *(float4*)&part[(g * 2 + 0) * 256 + col] = acc0;
        *(float4*)&part[(g * 2 + 1) * 256 + col] = acc1;
        __syncthreads();

        // reduce the 8 group-partials; thread owns (rb, rk).
        // All reads of old h completed before the barrier above, so writing
        // hs in place is safe; barrier 2 publishes the new h (and protects
        // part[] against next-step overwrite).
        float s = 0.0f;
#pragma unroll
        for (int gg = 0; gg < 8; gg++) s += part[(gg * 2 + rb) * 256 + rk];

        hn = tanhf(xv + s);
        if (rb == 0) hs0[rk] = hn; else hs1[rk] = hn;
        __syncthreads();
    }

    // final hidden state -> out [B, K]
    out[(size_t)(b0 + rb) * K_ + rk] = hn;
}

// =====================================================================
// Harness entry
// metadata order: inputs [B,T,D] f32, U [D,K] f32, W [K,K] f32, b [K] f32
// output: [B,1,K] f32
// =====================================================================
extern "C" void kernel_launch(void* const* d_in, const int* in_sizes, int n_in,
                              void* d_out, int out_size) {
    const float* X    = (const float*)d_in[0];
    const float* U    = (const float*)d_in[1];
    const float* W    = (const float*)d_in[2];
    const float* bias = (const float*)d_in[3];
    float* out = (float*)d_out;

    cudaError_t attr_rc = cudaFuncSetAttribute(
        rnn_recurrence_kernel,
        cudaFuncAttributeMaxDynamicSharedMemorySize,
        RNN_SMEM_BYTES);
    (void)attr_rc;

    dim3 gemm_grid(B_ * T_ / BM, K_ / BN);   // (1024, 2)
    xu_gemm_kernel<<<gemm_grid, 256>>>(X, U, bias);

    rnn_recurrence_kernel<<<128, 512, RNN_SMEM_BYTES>>>(W, out);
}